// round 6
// baseline (speedup 1.0000x reference)
#include <cuda_runtime.h>
#include <cuda_bf16.h>

// CenterLoss: out = mean_b ||features[b] - centers[labels[b]]||^2
// B = 65536, D = 256, C = 100000, LAMBDA_C = 1.0.
//
// Warp owns 2 consecutive rows. One 256-bit load (ld.global.nc.v4.b64) per
// lane covers 32B -> a full 1KB row per warp per instruction. 4 loads
// front-batched per warp (asm volatile order) = 32 dest regs, and
// __launch_bounds__(256, 4) grants a 64-reg budget so ptxas has NO incentive
// to serialize them (R3/R5 failure mode: 36-reg allocation inserted
// scoreboard waits between loads, MLP ~1).
// Centers: L2::evict_last (labels repeat across graph replays -> resident).
// Features: L2::evict_first (one-pass 64MB stream).
// Block partial -> last-block-done double reduction; wrapping atomic counter
// self-resets across replays.

#define D 256
#define WARPS_PER_BLOCK 8
#define ROWS_PER_WARP 2
#define NBLOCKS 4096   // 4096 * 8 warps * 2 rows = 65536 = B

__device__ float g_partials[NBLOCKS];
__device__ unsigned int g_ctr = 0;

struct V8 { unsigned long long u[4]; };

// Streamed 256-bit load (features: one-pass, evict first)
__device__ __forceinline__ V8 ld_stream(const void* p) {
    V8 v;
    asm volatile("ld.global.nc.L1::evict_first.L2::evict_first.v4.b64 {%0,%1,%2,%3}, [%4];"
                 : "=l"(v.u[0]), "=l"(v.u[1]), "=l"(v.u[2]), "=l"(v.u[3]) : "l"(p));
    return v;
}
// Sticky 256-bit load (centers: keep in L2 across replays)
__device__ __forceinline__ V8 ld_sticky(const void* p) {
    V8 v;
    asm volatile("ld.global.nc.L2::evict_last.v4.b64 {%0,%1,%2,%3}, [%4];"
                 : "=l"(v.u[0]), "=l"(v.u[1]), "=l"(v.u[2]), "=l"(v.u[3]) : "l"(p));
    return v;
}

// s += sum((a-b)^2) over the 8 packed floats
__device__ __forceinline__ float sq8(const V8& a, const V8& b, float s) {
    #pragma unroll
    for (int i = 0; i < 4; i++) {
        float2 af = *reinterpret_cast<const float2*>(&a.u[i]);
        float2 bf = *reinterpret_cast<const float2*>(&b.u[i]);
        float d0 = af.x - bf.x; s = fmaf(d0, d0, s);
        float d1 = af.y - bf.y; s = fmaf(d1, d1, s);
    }
    return s;
}

__global__ __launch_bounds__(WARPS_PER_BLOCK * 32, 4)   // 64-reg budget
void center_loss_fused(const float* __restrict__ feat,
                       const int* __restrict__ labels,
                       const float* __restrict__ centers,
                       float* __restrict__ out, int B) {
    const int warp = threadIdx.x >> 5;
    const int lane = threadIdx.x & 31;
    const int row0 = (blockIdx.x * WARPS_PER_BLOCK + warp) * ROWS_PER_WARP;

    // One broadcast int2 load: labels for both rows of this warp.
    const int2 lab = *reinterpret_cast<const int2*>(labels + row0);

    // Each lane owns bytes [lane*32, lane*32+32) of each 1KB row.
    const char* fbase = reinterpret_cast<const char*>(feat) + (size_t)row0 * D * 4 + lane * 32;
    const char* cbase = reinterpret_cast<const char*>(centers) + lane * 32;

    const void* c0 = cbase + (size_t)lab.x * (D * 4);
    const void* c1 = cbase + (size_t)lab.y * (D * 4);
    const void* f0 = fbase;
    const void* f1 = fbase + D * 4;

    // 4 loads front-batched (asm volatile preserves issue order).
    V8 b0 = ld_sticky(c0);
    V8 b1 = ld_sticky(c1);
    V8 a0 = ld_stream(f0);
    V8 a1 = ld_stream(f1);

    float s0 = sq8(a0, b0, 0.0f);
    float s1 = sq8(a1, b1, 0.0f);
    float acc = s0 + s1;

    // Warp reduction (fixed tree -> deterministic)
    #pragma unroll
    for (int o = 16; o > 0; o >>= 1)
        acc += __shfl_xor_sync(0xFFFFFFFFu, acc, o);

    __shared__ float s[WARPS_PER_BLOCK];
    __shared__ bool is_last;
    if (lane == 0) s[warp] = acc;
    __syncthreads();

    if (threadIdx.x == 0) {
        float t = 0.0f;
        #pragma unroll
        for (int i = 0; i < WARPS_PER_BLOCK; i++) t += s[i];
        g_partials[blockIdx.x] = t;
        __threadfence();
        unsigned int old = atomicInc(&g_ctr, gridDim.x - 1);  // wraps -> replay-safe
        is_last = (old == gridDim.x - 1);
    }
    __syncthreads();

    if (!is_last) return;

    // Last block: deterministic double-precision reduction of 4096 partials.
    __shared__ double sd[256];
    const volatile float* vp = g_partials;
    double t = 0.0;
    #pragma unroll 4
    for (int i = threadIdx.x; i < NBLOCKS; i += 256)
        t += (double)vp[i];
    sd[threadIdx.x] = t;
    __syncthreads();
    #pragma unroll
    for (int stride = 128; stride > 0; stride >>= 1) {
        if (threadIdx.x < stride) sd[threadIdx.x] += sd[threadIdx.x + stride];
        __syncthreads();
    }
    if (threadIdx.x == 0)
        out[0] = (float)(sd[0] / (double)B);   // LAMBDA_C = 1.0
}

extern "C" void kernel_launch(void* const* d_in, const int* in_sizes, int n_in,
                              void* d_out, int out_size) {
    const float* feat    = (const float*)d_in[0];
    const int*   labels  = (const int*)d_in[1];
    const float* centers = (const float*)d_in[2];
    float*       out     = (float*)d_out;

    const int B = in_sizes[1];   // 65536

    center_loss_fused<<<NBLOCKS, WARPS_PER_BLOCK * 32>>>(feat, labels, centers, out, B);
}